// round 13
// baseline (speedup 1.0000x reference)
#include <cuda_runtime.h>
#include <cuda_bf16.h>
#include <cstdint>

// Problem constants
#define BATCH 4096
#define DIN   256
#define DOUT  256
#define NEXP  64

#define NHALF 128        // N cols per CTA (2 CTAs per expert)
#define MCH   96         // M rows per chunk
#define NTHREADS 256
#define RCAP  192

// smem byte offsets (dynamic)
#define S_WH   0                   // W hi: [256 k][128 n] bf16, 256B rows = 64KB
#define S_WL   65536               // W lo
#define S_XH   131072              // x hi: [96 m][256 k] bf16, 512B rows = 48KB
#define S_XL   180224              // x lo
#define S_BIAS 229376              // 128 floats
#define S_ROWS 229888              // RCAP ints
#define S_CNT  230656
#define SMEM_BYTES 230912

// fp32 W staging scratch (double buffer) in the XH/XL region (free until x staged)
#define S_SCR0 131072
#define S_SCR1 163840

__device__ int g_sel[BATCH];   // pure function of onehot; rewritten every launch

// ---------------------------------------------------------------------------
__device__ __forceinline__ uint32_t bf2(float lo, float hi) {
    uint32_t r;
    asm("cvt.rn.bf16x2.f32 %0, %1, %2;" : "=r"(r) : "f"(hi), "f"(lo));
    return r;
}
__device__ __forceinline__ float bflo_f(uint32_t p) { return __uint_as_float(p << 16); }
__device__ __forceinline__ float bfhi_f(uint32_t p) { return __uint_as_float(p & 0xffff0000u); }

__device__ __forceinline__ uint32_t smem_to_u32(const void* p) {
    uint32_t a;
    asm("{ .reg .u64 t; cvta.to.shared.u64 t, %1; cvt.u32.u64 %0, t; }"
        : "=r"(a) : "l"(p));
    return a;
}

#define CP_ASYNC16(DST, SRC) \
    asm volatile("cp.async.cg.shared.global [%0], [%1], 16;" \
                 :: "r"(DST), "l"(SRC))
#define CP_COMMIT() asm volatile("cp.async.commit_group;")
#define CP_WAIT(N)  asm volatile("cp.async.wait_group %0;" :: "n"(N))

#define LDSM4(R, ADDR) \
    asm volatile("ldmatrix.sync.aligned.m8n8.x4.shared.b16 {%0,%1,%2,%3}, [%4];" \
        : "=r"((R)[0]), "=r"((R)[1]), "=r"((R)[2]), "=r"((R)[3]) : "r"(ADDR))

#define LDSM4T(R, ADDR) \
    asm volatile("ldmatrix.sync.aligned.m8n8.x4.trans.shared.b16 {%0,%1,%2,%3}, [%4];" \
        : "=r"((R)[0]), "=r"((R)[1]), "=r"((R)[2]), "=r"((R)[3]) : "r"(ADDR))

#define MMA16816(D, A, B0, B1) \
    asm volatile("mma.sync.aligned.m16n8k16.row.col.f32.bf16.bf16.f32 " \
        "{%0,%1,%2,%3}, {%4,%5,%6,%7}, {%8,%9}, {%0,%1,%2,%3};" \
        : "+r"((D)[0]), "+r"((D)[1]), "+r"((D)[2]), "+r"((D)[3]) \
        : "r"((A)[0]), "r"((A)[1]), "r"((A)[2]), "r"((A)[3]), "r"(B0), "r"(B1))

// ---------------------------------------------------------------------------
// Kernel 1: coalesced selector decode -> g_sel[b]. grid 16 x 256 threads.
// Each block reads a contiguous 64KB slab of onehot as float4 (nL=1 per LDG).
// Every row has exactly one hot element -> exactly one write per row.
// ---------------------------------------------------------------------------
__global__ void presel_kernel(const float* __restrict__ onehot) {
    const int base = blockIdx.x * 256;   // row base of this slab
    const float4* slab = (const float4*)(onehot + ((size_t)base << 6));
    const int tid = threadIdx.x;
#pragma unroll
    for (int it = 0; it < 16; it++) {
        int u  = tid + 256 * it;     // float4 index in slab (coalesced)
        int r  = u >> 4;             // row within slab
        int c4 = (u & 15) << 2;      // expert base of this quad
        float4 v = slab[u];
        int sel = -1;
        if (v.x > 0.5f) sel = c4 + 0;
        if (v.y > 0.5f) sel = c4 + 1;
        if (v.z > 0.5f) sel = c4 + 2;
        if (v.w > 0.5f) sel = c4 + 3;
        if (sel >= 0) g_sel[base + r] = sel;
    }
}

// ---------------------------------------------------------------------------
// Kernel 2: fused grouped GEMM. blockIdx.y = expert, blockIdx.x = n-half.
// 8 warps: warp grid 2m x 4n; warp tile 48m x 32n.
// 3-term bf16 split in fp32: xh*Wh + xh*Wl + xl*Wh.
// ---------------------------------------------------------------------------
__global__ void __launch_bounds__(NTHREADS, 1)
gemm_kernel(const float* __restrict__ x,
            const float* __restrict__ W,
            const float* __restrict__ Bw,
            float* __restrict__ out) {
    extern __shared__ char smem[];
    const uint32_t sb = smem_to_u32(smem);
    float* s_bias = (float*)(smem + S_BIAS);
    int*   s_rows = (int*)(smem + S_ROWS);
    int*   s_cnt  = (int*)(smem + S_CNT);

    const int tid  = threadIdx.x;
    const int lane = tid & 31;
    const int wid  = tid >> 5;
    const int e    = blockIdx.y;
    const int n0   = blockIdx.x * NHALF;

    if (tid == 0) *s_cnt = 0;

    const float* We = W + ((size_t)e << 16) + n0;   // W[e][k][n0..]

    // issue W quarters 0 and 1 (each: 64 k-rows x 512B = 2048 16B chunks)
#pragma unroll
    for (int j = 0; j < 8; j++) {
        int c = tid + 256 * j;
        CP_ASYNC16(sb + S_SCR0 + c * 16,
                   We + ((size_t)(c >> 5) << 8) + ((c & 31) << 2));
    }
    CP_COMMIT();
#pragma unroll
    for (int j = 0; j < 8; j++) {
        int c = tid + 256 * j;
        CP_ASYNC16(sb + S_SCR1 + c * 16,
                   We + ((size_t)(64 + (c >> 5)) << 8) + ((c & 31) << 2));
    }
    CP_COMMIT();

    // --- coalesced selector read: 16 ints per thread (4 LDG.128, nL=1) ---
    int4 sv[4];
#pragma unroll
    for (int j = 0; j < 4; j++)
        sv[j] = ((const int4*)g_sel)[tid + 256 * j];

    if (tid < NHALF) s_bias[tid] = Bw[(e << 8) + n0 + tid];

    __syncthreads();   // s_cnt init visible

    // --- compact this expert's rows (order irrelevant) ---
#pragma unroll
    for (int j = 0; j < 4; j++) {
        int rb = (tid + 256 * j) << 2;
        if (sv[j].x == e) { int p = atomicAdd(s_cnt, 1); if (p < RCAP) s_rows[p] = rb + 0; }
        if (sv[j].y == e) { int p = atomicAdd(s_cnt, 1); if (p < RCAP) s_rows[p] = rb + 1; }
        if (sv[j].z == e) { int p = atomicAdd(s_cnt, 1); if (p < RCAP) s_rows[p] = rb + 2; }
        if (sv[j].w == e) { int p = atomicAdd(s_cnt, 1); if (p < RCAP) s_rows[p] = rb + 3; }
    }

    // --- convert W quarters (fp32 scratch -> bf16 hi/lo swizzled), pipelined ---
#pragma unroll 1
    for (int q = 0; q < 4; q++) {
        if (q < 2) { CP_WAIT(1); } else { CP_WAIT(0); }
        __syncthreads();   // quarter q visible to all threads
        const float4* scr4 = (const float4*)(smem + ((q & 1) ? S_SCR1 : S_SCR0));
#pragma unroll
        for (int j = 0; j < 4; j++) {
            int g  = tid + 256 * j;     // 0..1023 granules (8 floats)
            int kq = g >> 4;            // 0..63
            int nc = g & 15;
            float4 v0 = scr4[kq * 32 + nc * 2];
            float4 v1 = scr4[kq * 32 + nc * 2 + 1];
            uint32_t h0 = bf2(v0.x, v0.y), h1 = bf2(v0.z, v0.w);
            uint32_t h2 = bf2(v1.x, v1.y), h3 = bf2(v1.z, v1.w);
            uint32_t l0 = bf2(v0.x - bflo_f(h0), v0.y - bfhi_f(h0));
            uint32_t l1 = bf2(v0.z - bflo_f(h1), v0.w - bfhi_f(h1));
            uint32_t l2 = bf2(v1.x - bflo_f(h2), v1.y - bfhi_f(h2));
            uint32_t l3 = bf2(v1.z - bflo_f(h3), v1.w - bfhi_f(h3));
            int k = 64 * q + kq;
            uint32_t gsw = (uint32_t)((nc & 8) | ((nc & 7) ^ (k & 7)));
            uint32_t dst = ((uint32_t)k << 8) + (gsw << 4);
            *(uint4*)(smem + S_WH + dst) = make_uint4(h0, h1, h2, h3);
            *(uint4*)(smem + S_WL + dst) = make_uint4(l0, l1, l2, l3);
        }
        if (q < 2) {
            __syncthreads();   // all converts of q done before reusing buffer
            int kbase = 64 * (q + 2);
#pragma unroll
            for (int j = 0; j < 8; j++) {
                int c = tid + 256 * j;
                CP_ASYNC16(sb + ((q & 1) ? S_SCR1 : S_SCR0) + c * 16,
                           We + ((size_t)(kbase + (c >> 5)) << 8) + ((c & 31) << 2));
            }
            CP_COMMIT();
        }
    }
    __syncthreads();   // WH/WL + s_rows/s_cnt ready; scratch free for x

    const int cnt = min(*s_cnt, RCAP);

    // warp/lane geometry
    const int mw0 = (wid >> 2) * 48;               // 0 or 48
    const int nw0 = (wid & 3) * 32;                // 0,32,64,96
    const int lm    = lane & 15;
    const int lhalf = lane >> 4;
    const int l7    = lane & 7;

    uint32_t aBaseH[3], aBaseL[3];
#pragma unroll
    for (int i = 0; i < 3; i++) {
        uint32_t roff = (uint32_t)(mw0 + 16 * i + lm) << 9;
        aBaseH[i] = sb + S_XH + roff;
        aBaseL[i] = sb + S_XL + roff;
    }
    const uint32_t bRowOff = (uint32_t)lm << 8;
    const int ncA = (wid & 3) * 4 + lhalf;
    const int ncB = ncA + 2;
    const uint32_t gswBA = (uint32_t)((ncA & 8) | ((ncA & 7) ^ l7)) << 4;
    const uint32_t gswBB = (uint32_t)((ncB & 8) | ((ncB & 7) ^ l7)) << 4;
    const uint32_t bBaseH = sb + S_WH + bRowOff;
    const uint32_t bBaseL = sb + S_WL + bRowOff;

    for (int m0 = 0; m0 < cnt; m0 += MCH) {
        const int nrows = min(MCH, cnt - m0);

        // --- stage x chunk [96m][256k]: fp32 -> bf16 hi/lo, swizzled ---
#pragma unroll
        for (int it = 0; it < 12; it++) {
            int u = tid + NTHREADS * it;    // 0..3071
            int r = u >> 5;                 // 0..95
            int c = u & 31;                 // 8-float chunk
            float4 v0, v1;
            if (r < nrows) {
                const float4* xr = (const float4*)(x + ((size_t)s_rows[m0 + r] << 8));
                v0 = xr[2 * c]; v1 = xr[2 * c + 1];
            } else {
                v0 = make_float4(0.f, 0.f, 0.f, 0.f);
                v1 = v0;
            }
            uint32_t h0 = bf2(v0.x, v0.y), h1 = bf2(v0.z, v0.w);
            uint32_t h2 = bf2(v1.x, v1.y), h3 = bf2(v1.z, v1.w);
            uint32_t l0 = bf2(v0.x - bflo_f(h0), v0.y - bfhi_f(h0));
            uint32_t l1 = bf2(v0.z - bflo_f(h1), v0.w - bfhi_f(h1));
            uint32_t l2 = bf2(v1.x - bflo_f(h2), v1.y - bfhi_f(h2));
            uint32_t l3 = bf2(v1.z - bflo_f(h3), v1.w - bfhi_f(h3));
            uint32_t gsw = (uint32_t)((c & 24) | ((c & 7) ^ (r & 7)));
            uint32_t dst = ((uint32_t)r << 9) + (gsw << 4);
            *(uint4*)(smem + S_XH + dst) = make_uint4(h0, h1, h2, h3);
            *(uint4*)(smem + S_XL + dst) = make_uint4(l0, l1, l2, l3);
        }
        __syncthreads();

        // --- mma mainloop: D[3 m-frags][4 n-frags] fp32 ---
        uint32_t d[3][4][4];
#pragma unroll
        for (int i = 0; i < 3; i++)
#pragma unroll
            for (int j = 0; j < 4; j++)
#pragma unroll
                for (int q = 0; q < 4; q++) d[i][j][q] = 0u;

#pragma unroll 2
        for (int ks = 0; ks < 16; ks++) {
            int gA = 2 * ks + lhalf;   // A k-granule 0..31
            uint32_t swA = (uint32_t)((gA & 24) | ((gA & 7) ^ l7)) << 4;
            uint32_t bK = (uint32_t)ks << 12;   // 16 k-rows * 256B

            uint32_t ah[3][4], al[3][4];
#pragma unroll
            for (int i = 0; i < 3; i++) {
                LDSM4(ah[i], aBaseH[i] + swA);
                LDSM4(al[i], aBaseL[i] + swA);
            }
            uint32_t bh[8], bl[8];
            LDSM4T(bh,     bBaseH + bK + gswBA);
            LDSM4T(bh + 4, bBaseH + bK + gswBB);
            LDSM4T(bl,     bBaseL + bK + gswBA);
            LDSM4T(bl + 4, bBaseL + bK + gswBB);

#pragma unroll
            for (int i = 0; i < 3; i++)
#pragma unroll
                for (int j = 0; j < 4; j++) {
                    MMA16816(d[i][j], ah[i], bh[2 * j], bh[2 * j + 1]);
                    MMA16816(d[i][j], ah[i], bl[2 * j], bl[2 * j + 1]);
                    MMA16816(d[i][j], al[i], bh[2 * j], bh[2 * j + 1]);
                }
        }

        // --- epilogue: add bias, scatter rows ---
#pragma unroll
        for (int i = 0; i < 3; i++) {
            int rlo = mw0 + 16 * i + (lane >> 2);
#pragma unroll
            for (int half = 0; half < 2; half++) {
                int m = m0 + rlo + 8 * half;
                if (m < cnt) {
                    float* op = out + ((size_t)s_rows[m] << 8) + n0;
#pragma unroll
                    for (int j = 0; j < 4; j++) {
                        int c = nw0 + 8 * j + 2 * (lane & 3);
                        float2 b = *(float2*)(s_bias + c);
                        float2 v;
                        v.x = __uint_as_float(d[i][j][2 * half + 0]) + b.x;
                        v.y = __uint_as_float(d[i][j][2 * half + 1]) + b.y;
                        *(float2*)(op + c) = v;
                    }
                }
            }
        }
        __syncthreads();   // before next chunk overwrites s_x
    }
}

// ---------------------------------------------------------------------------
extern "C" void kernel_launch(void* const* d_in, const int* in_sizes, int n_in,
                              void* d_out, int out_size) {
    const float* x      = (const float*)d_in[0];
    const float* onehot = (const float*)d_in[1];
    const float* W      = (const float*)d_in[2];
    const float* Bw     = (const float*)d_in[3];
    float* out          = (float*)d_out;

    cudaFuncSetAttribute(gemm_kernel,
                         cudaFuncAttributeMaxDynamicSharedMemorySize,
                         SMEM_BYTES);

    presel_kernel<<<BATCH / 256, 256>>>(onehot);
    gemm_kernel<<<dim3(DOUT / NHALF, NEXP), NTHREADS, SMEM_BYTES>>>(x, W, Bw, out);
}

// round 14
// speedup vs baseline: 1.4024x; 1.4024x over previous
#include <cuda_runtime.h>
#include <cuda_bf16.h>
#include <cstdint>

// Problem constants
#define BATCH 4096
#define DIN   256
#define DOUT  256
#define NEXP  64

#define NHALF 128        // N cols per CTA (2 CTAs per expert)
#define MCH   96         // M rows per chunk
#define NTHREADS 256
#define RCAP  192
#define NCTAS 128        // total CTAs (one wave; co-resident)

// smem byte offsets (dynamic)
#define S_WH   0                   // W hi: [256 k][128 n] bf16, 256B rows = 64KB
#define S_WL   65536               // W lo
#define S_XH   131072              // x hi: [96 m][256 k] bf16, 512B rows = 48KB
#define S_XL   180224              // x lo
#define S_BIAS 229376              // 128 floats
#define S_ROWS 229888              // RCAP ints
#define S_CNT  230656
#define SMEM_BYTES 230912

__device__ int g_sel[BATCH];   // decoded selector (rewritten every launch)
__device__ int g_arrive;       // decode barrier; reset by last-done CTA
__device__ int g_done;         // end-of-kernel arrival counter

// ---------------------------------------------------------------------------
__device__ __forceinline__ uint32_t bf2(float lo, float hi) {
    uint32_t r;
    asm("cvt.rn.bf16x2.f32 %0, %1, %2;" : "=r"(r) : "f"(hi), "f"(lo));
    return r;
}
__device__ __forceinline__ float bflo_f(uint32_t p) { return __uint_as_float(p << 16); }
__device__ __forceinline__ float bfhi_f(uint32_t p) { return __uint_as_float(p & 0xffff0000u); }

__device__ __forceinline__ uint32_t smem_to_u32(const void* p) {
    uint32_t a;
    asm("{ .reg .u64 t; cvta.to.shared.u64 t, %1; cvt.u32.u64 %0, t; }"
        : "=r"(a) : "l"(p));
    return a;
}

#define LDSM4(R, ADDR) \
    asm volatile("ldmatrix.sync.aligned.m8n8.x4.shared.b16 {%0,%1,%2,%3}, [%4];" \
        : "=r"((R)[0]), "=r"((R)[1]), "=r"((R)[2]), "=r"((R)[3]) : "r"(ADDR))

#define LDSM4T(R, ADDR) \
    asm volatile("ldmatrix.sync.aligned.m8n8.x4.trans.shared.b16 {%0,%1,%2,%3}, [%4];" \
        : "=r"((R)[0]), "=r"((R)[1]), "=r"((R)[2]), "=r"((R)[3]) : "r"(ADDR))

#define MMA16816(D, A, B0, B1) \
    asm volatile("mma.sync.aligned.m16n8k16.row.col.f32.bf16.bf16.f32 " \
        "{%0,%1,%2,%3}, {%4,%5,%6,%7}, {%8,%9}, {%0,%1,%2,%3};" \
        : "+r"((D)[0]), "+r"((D)[1]), "+r"((D)[2]), "+r"((D)[3]) \
        : "r"((A)[0]), "r"((A)[1]), "r"((A)[2]), "r"((A)[3]), "r"(B0), "r"(B1))

// ---------------------------------------------------------------------------
// Single fused kernel. blockIdx.y = expert, blockIdx.x = n-half. 8 warps.
// Phases: [all] decode own 32-row onehot slab -> g_sel; then
//   warps 0-3: convert W (gmem fp32 -> smem bf16 hi/lo, swizzled)
//   warps 4-7: device barrier -> compact g_sel -> stage x chunk 0
// join -> 48x32-warp-tile HMMA (3-term bf16 split) -> epilogue.
// ---------------------------------------------------------------------------
__global__ void __launch_bounds__(NTHREADS, 1)
gemm_kernel(const float* __restrict__ x,
            const float* __restrict__ onehot,
            const float* __restrict__ W,
            const float* __restrict__ Bw,
            float* __restrict__ out) {
    extern __shared__ char smem[];
    const uint32_t sb = smem_to_u32(smem);
    float* s_bias = (float*)(smem + S_BIAS);
    int*   s_rows = (int*)(smem + S_ROWS);
    int*   s_cnt  = (int*)(smem + S_CNT);

    const int tid  = threadIdx.x;
    const int lane = tid & 31;
    const int wid  = tid >> 5;
    const int e    = blockIdx.y;
    const int n0   = blockIdx.x * NHALF;
    const int cid  = blockIdx.y * gridDim.x + blockIdx.x;   // 0..127

    if (tid == 0) *s_cnt = 0;

    // --- decode this CTA's 32-row slab of onehot (fully coalesced) ---
    {
        const float4* slab = (const float4*)(onehot + ((size_t)cid << 11));
#pragma unroll
        for (int j = 0; j < 2; j++) {
            int u  = tid + 256 * j;      // 0..511 float4 granules
            int r  = u >> 4;             // row within slab (0..31)
            int c4 = (u & 15) << 2;      // expert base of this quad
            float4 v = slab[u];
            int sel = -1;
            if (v.x > 0.5f) sel = c4 + 0;
            if (v.y > 0.5f) sel = c4 + 1;
            if (v.z > 0.5f) sel = c4 + 2;
            if (v.w > 0.5f) sel = c4 + 3;
            if (sel >= 0) g_sel[cid * 32 + r] = sel;
        }
    }
    if (tid < NHALF) s_bias[tid] = Bw[(e << 8) + n0 + tid];

    __threadfence();       // publish g_sel slice (gpu scope)
    __syncthreads();       // all decode writes + fences done; s_cnt init visible
    if (tid == 0) atomicAdd(&g_arrive, 1);

    if (tid < 128) {
        // ---- warps 0-3: convert W tile [256k][128n] to bf16 hi/lo swizzled ----
        const float* We = W + ((size_t)e << 16) + n0;
#pragma unroll
        for (int it = 0; it < 32; it++) {
            int u  = tid + 128 * it;    // 0..4095 granules (8 floats)
            int k  = u >> 4;
            int nc = u & 15;
            const float* src = We + ((size_t)k << 8) + (nc << 3);
            float4 v0 = *(const float4*)(src);
            float4 v1 = *(const float4*)(src + 4);
            uint32_t h0 = bf2(v0.x, v0.y), h1 = bf2(v0.z, v0.w);
            uint32_t h2 = bf2(v1.x, v1.y), h3 = bf2(v1.z, v1.w);
            uint32_t l0 = bf2(v0.x - bflo_f(h0), v0.y - bfhi_f(h0));
            uint32_t l1 = bf2(v0.z - bflo_f(h1), v0.w - bfhi_f(h1));
            uint32_t l2 = bf2(v1.x - bflo_f(h2), v1.y - bfhi_f(h2));
            uint32_t l3 = bf2(v1.z - bflo_f(h3), v1.w - bfhi_f(h3));
            uint32_t gsw = (uint32_t)((nc & 8) | ((nc & 7) ^ (k & 7)));
            uint32_t dst = ((uint32_t)k << 8) + (gsw << 4);
            *(uint4*)(smem + S_WH + dst) = make_uint4(h0, h1, h2, h3);
            *(uint4*)(smem + S_WL + dst) = make_uint4(l0, l1, l2, l3);
        }
    } else {
        // ---- warps 4-7: barrier, compact rows, stage x chunk 0 ----
        const int t = tid - 128;
        if (t == 0) {
            while (*(volatile int*)&g_arrive < NCTAS) { __nanosleep(64); }
        }
        asm volatile("bar.sync 3, 128;" ::: "memory");
        __threadfence();   // acquire side: g_sel writes visible

        int4 sv[8];
#pragma unroll
        for (int j = 0; j < 8; j++)
            sv[j] = ((const int4*)g_sel)[t + 128 * j];
#pragma unroll
        for (int j = 0; j < 8; j++) {
            int rb = (t + 128 * j) << 2;
            if (sv[j].x == e) { int p = atomicAdd(s_cnt, 1); if (p < RCAP) s_rows[p] = rb + 0; }
            if (sv[j].y == e) { int p = atomicAdd(s_cnt, 1); if (p < RCAP) s_rows[p] = rb + 1; }
            if (sv[j].z == e) { int p = atomicAdd(s_cnt, 1); if (p < RCAP) s_rows[p] = rb + 2; }
            if (sv[j].w == e) { int p = atomicAdd(s_cnt, 1); if (p < RCAP) s_rows[p] = rb + 3; }
        }
        asm volatile("bar.sync 3, 128;" ::: "memory");   // s_rows complete
        const int nrows0 = min(min(*s_cnt, RCAP), MCH);

        // stage x chunk 0: [96m][256k] fp32 -> bf16 hi/lo swizzled
#pragma unroll
        for (int it = 0; it < 24; it++) {
            int u = t + 128 * it;       // 0..3071
            int r = u >> 5;             // 0..95
            int c = u & 31;             // 8-float chunk
            float4 v0, v1;
            if (r < nrows0) {
                const float4* xr = (const float4*)(x + ((size_t)s_rows[r] << 8));
                v0 = xr[2 * c]; v1 = xr[2 * c + 1];
            } else {
                v0 = make_float4(0.f, 0.f, 0.f, 0.f);
                v1 = v0;
            }
            uint32_t h0 = bf2(v0.x, v0.y), h1 = bf2(v0.z, v0.w);
            uint32_t h2 = bf2(v1.x, v1.y), h3 = bf2(v1.z, v1.w);
            uint32_t l0 = bf2(v0.x - bflo_f(h0), v0.y - bfhi_f(h0));
            uint32_t l1 = bf2(v0.z - bflo_f(h1), v0.w - bfhi_f(h1));
            uint32_t l2 = bf2(v1.x - bflo_f(h2), v1.y - bfhi_f(h2));
            uint32_t l3 = bf2(v1.z - bflo_f(h3), v1.w - bfhi_f(h3));
            uint32_t gsw = (uint32_t)((c & 24) | ((c & 7) ^ (r & 7)));
            uint32_t dst = ((uint32_t)r << 9) + (gsw << 4);
            *(uint4*)(smem + S_XH + dst) = make_uint4(h0, h1, h2, h3);
            *(uint4*)(smem + S_XL + dst) = make_uint4(l0, l1, l2, l3);
        }
    }
    __syncthreads();   // W tiles + x chunk 0 + s_rows/s_cnt all ready

    const int cnt = min(*s_cnt, RCAP);

    // warp/lane geometry
    const int mw0 = (wid >> 2) * 48;               // 0 or 48
    const int nw0 = (wid & 3) * 32;                // 0,32,64,96
    const int lm    = lane & 15;
    const int lhalf = lane >> 4;
    const int l7    = lane & 7;

    uint32_t aBaseH[3], aBaseL[3];
#pragma unroll
    for (int i = 0; i < 3; i++) {
        uint32_t roff = (uint32_t)(mw0 + 16 * i + lm) << 9;
        aBaseH[i] = sb + S_XH + roff;
        aBaseL[i] = sb + S_XL + roff;
    }
    const uint32_t bRowOff = (uint32_t)lm << 8;
    const int ncA = (wid & 3) * 4 + lhalf;
    const int ncB = ncA + 2;
    const uint32_t gswBA = (uint32_t)((ncA & 8) | ((ncA & 7) ^ l7)) << 4;
    const uint32_t gswBB = (uint32_t)((ncB & 8) | ((ncB & 7) ^ l7)) << 4;
    const uint32_t bBaseH = sb + S_WH + bRowOff;
    const uint32_t bBaseL = sb + S_WL + bRowOff;

    int m0 = 0;
    while (true) {
        // --- mma mainloop over staged chunk: D[3 m][4 n] fp32 ---
        uint32_t d[3][4][4];
#pragma unroll
        for (int i = 0; i < 3; i++)
#pragma unroll
            for (int j = 0; j < 4; j++)
#pragma unroll
                for (int q = 0; q < 4; q++) d[i][j][q] = 0u;

#pragma unroll 2
        for (int ks = 0; ks < 16; ks++) {
            int gA = 2 * ks + lhalf;
            uint32_t swA = (uint32_t)((gA & 24) | ((gA & 7) ^ l7)) << 4;
            uint32_t bK = (uint32_t)ks << 12;

            uint32_t ah[3][4], al[3][4];
#pragma unroll
            for (int i = 0; i < 3; i++) {
                LDSM4(ah[i], aBaseH[i] + swA);
                LDSM4(al[i], aBaseL[i] + swA);
            }
            uint32_t bh[8], bl[8];
            LDSM4T(bh,     bBaseH + bK + gswBA);
            LDSM4T(bh + 4, bBaseH + bK + gswBB);
            LDSM4T(bl,     bBaseL + bK + gswBA);
            LDSM4T(bl + 4, bBaseL + bK + gswBB);

#pragma unroll
            for (int i = 0; i < 3; i++)
#pragma unroll
                for (int j = 0; j < 4; j++) {
                    MMA16816(d[i][j], ah[i], bh[2 * j], bh[2 * j + 1]);
                    MMA16816(d[i][j], ah[i], bl[2 * j], bl[2 * j + 1]);
                    MMA16816(d[i][j], al[i], bh[2 * j], bh[2 * j + 1]);
                }
        }

        // --- epilogue: add bias, scatter rows ---
#pragma unroll
        for (int i = 0; i < 3; i++) {
            int rlo = mw0 + 16 * i + (lane >> 2);
#pragma unroll
            for (int half = 0; half < 2; half++) {
                int m = m0 + rlo + 8 * half;
                if (m < cnt) {
                    float* op = out + ((size_t)s_rows[m] << 8) + n0;
#pragma unroll
                    for (int j = 0; j < 4; j++) {
                        int c = nw0 + 8 * j + 2 * (lane & 3);
                        float2 b = *(float2*)(s_bias + c);
                        float2 v;
                        v.x = __uint_as_float(d[i][j][2 * half + 0]) + b.x;
                        v.y = __uint_as_float(d[i][j][2 * half + 1]) + b.y;
                        *(float2*)(op + c) = v;
                    }
                }
            }
        }

        m0 += MCH;
        if (m0 >= cnt) break;

        // --- rare second chunk: stage by all 256 threads ---
        __syncthreads();
        const int nrows = min(MCH, cnt - m0);
#pragma unroll
        for (int it = 0; it < 12; it++) {
            int u = tid + NTHREADS * it;
            int r = u >> 5;
            int c = u & 31;
            float4 v0, v1;
            if (r < nrows) {
                const float4* xr = (const float4*)(x + ((size_t)s_rows[m0 + r] << 8));
                v0 = xr[2 * c]; v1 = xr[2 * c + 1];
            } else {
                v0 = make_float4(0.f, 0.f, 0.f, 0.f);
                v1 = v0;
            }
            uint32_t h0 = bf2(v0.x, v0.y), h1 = bf2(v0.z, v0.w);
            uint32_t h2 = bf2(v1.x, v1.y), h3 = bf2(v1.z, v1.w);
            uint32_t l0 = bf2(v0.x - bflo_f(h0), v0.y - bfhi_f(h0));
            uint32_t l1 = bf2(v0.z - bflo_f(h1), v0.w - bfhi_f(h1));
            uint32_t l2 = bf2(v1.x - bflo_f(h2), v1.y - bfhi_f(h2));
            uint32_t l3 = bf2(v1.z - bflo_f(h3), v1.w - bfhi_f(h3));
            uint32_t gsw = (uint32_t)((c & 24) | ((c & 7) ^ (r & 7)));
            uint32_t dst = ((uint32_t)r << 9) + (gsw << 4);
            *(uint4*)(smem + S_XH + dst) = make_uint4(h0, h1, h2, h3);
            *(uint4*)(smem + S_XL + dst) = make_uint4(l0, l1, l2, l3);
        }
        __syncthreads();
    }

    // --- reset barrier counters for next graph replay ---
    if (tid == 0) {
        __threadfence();
        int od = atomicAdd(&g_done, 1);
        if (od == NCTAS - 1) {
            g_arrive = 0;
            g_done = 0;
            __threadfence();
        }
    }
}

// ---------------------------------------------------------------------------
extern "C" void kernel_launch(void* const* d_in, const int* in_sizes, int n_in,
                              void* d_out, int out_size) {
    const float* x      = (const float*)d_in[0];
    const float* onehot = (const float*)d_in[1];
    const float* W      = (const float*)d_in[2];
    const float* Bw     = (const float*)d_in[3];
    float* out          = (float*)d_out;

    cudaFuncSetAttribute(gemm_kernel,
                         cudaFuncAttributeMaxDynamicSharedMemorySize,
                         SMEM_BYTES);

    gemm_kernel<<<dim3(DOUT / NHALF, NEXP), NTHREADS, SMEM_BYTES>>>(
        x, onehot, W, Bw, out);
}

// round 15
// speedup vs baseline: 1.5359x; 1.0952x over previous
#include <cuda_runtime.h>
#include <cuda_bf16.h>
#include <cstdint>

// Problem constants
#define BATCH 4096
#define DIN   256
#define DOUT  256
#define NEXP  64

#define NHALF 128        // N cols per CTA (2 CTAs per expert)
#define MCH   96         // M rows per chunk
#define NTHREADS 512     // 16 warps = 4 per SMSP
#define RCAP  192
#define NCTAS 128        // total CTAs (one wave; co-resident)

// smem byte offsets (dynamic)
#define S_WH   0                   // W hi: [256 k][128 n] bf16, 256B rows = 64KB
#define S_WL   65536               // W lo
#define S_XH   131072              // x hi: [96 m][256 k] bf16, 512B rows = 48KB
#define S_XL   180224              // x lo
#define S_BIAS 229376              // 128 floats
#define S_ROWS 229888              // RCAP ints
#define S_CNT  230656
#define SMEM_BYTES 230912

__device__ int g_sel[BATCH];   // decoded selector (rewritten every launch)
__device__ int g_arrive;       // decode barrier; reset by last-done CTA
__device__ int g_done;         // end-of-kernel arrival counter

// ---------------------------------------------------------------------------
__device__ __forceinline__ uint32_t bf2(float lo, float hi) {
    uint32_t r;
    asm("cvt.rn.bf16x2.f32 %0, %1, %2;" : "=r"(r) : "f"(hi), "f"(lo));
    return r;
}
__device__ __forceinline__ float bflo_f(uint32_t p) { return __uint_as_float(p << 16); }
__device__ __forceinline__ float bfhi_f(uint32_t p) { return __uint_as_float(p & 0xffff0000u); }

__device__ __forceinline__ uint32_t smem_to_u32(const void* p) {
    uint32_t a;
    asm("{ .reg .u64 t; cvta.to.shared.u64 t, %1; cvt.u32.u64 %0, t; }"
        : "=r"(a) : "l"(p));
    return a;
}

#define LDSM4(R, ADDR) \
    asm volatile("ldmatrix.sync.aligned.m8n8.x4.shared.b16 {%0,%1,%2,%3}, [%4];" \
        : "=r"((R)[0]), "=r"((R)[1]), "=r"((R)[2]), "=r"((R)[3]) : "r"(ADDR))

#define LDSM4T(R, ADDR) \
    asm volatile("ldmatrix.sync.aligned.m8n8.x4.trans.shared.b16 {%0,%1,%2,%3}, [%4];" \
        : "=r"((R)[0]), "=r"((R)[1]), "=r"((R)[2]), "=r"((R)[3]) : "r"(ADDR))

#define MMA16816(D, A, B0, B1) \
    asm volatile("mma.sync.aligned.m16n8k16.row.col.f32.bf16.bf16.f32 " \
        "{%0,%1,%2,%3}, {%4,%5,%6,%7}, {%8,%9}, {%0,%1,%2,%3};" \
        : "+r"((D)[0]), "+r"((D)[1]), "+r"((D)[2]), "+r"((D)[3]) \
        : "r"((A)[0]), "r"((A)[1]), "r"((A)[2]), "r"((A)[3]), "r"(B0), "r"(B1))

// ---------------------------------------------------------------------------
// Single fused kernel. blockIdx.y = expert, blockIdx.x = n-half. 16 warps.
// Phases: [all] decode own 32-row onehot slab -> g_sel; then
//   warps 0-7 : convert W (gmem fp32 -> smem bf16 hi/lo, swizzled)
//   warps 8-15: device barrier -> compact g_sel -> stage x chunk 0
// join -> 48x16-warp-tile HMMA (3-term bf16 split) -> epilogue.
// ---------------------------------------------------------------------------
__global__ void __launch_bounds__(NTHREADS, 1)
gemm_kernel(const float* __restrict__ x,
            const float* __restrict__ onehot,
            const float* __restrict__ W,
            const float* __restrict__ Bw,
            float* __restrict__ out) {
    extern __shared__ char smem[];
    const uint32_t sb = smem_to_u32(smem);
    float* s_bias = (float*)(smem + S_BIAS);
    int*   s_rows = (int*)(smem + S_ROWS);
    int*   s_cnt  = (int*)(smem + S_CNT);

    const int tid  = threadIdx.x;
    const int lane = tid & 31;
    const int wid  = tid >> 5;
    const int e    = blockIdx.y;
    const int n0   = blockIdx.x * NHALF;
    const int cid  = blockIdx.y * gridDim.x + blockIdx.x;   // 0..127

    if (tid == 0) *s_cnt = 0;

    // --- decode this CTA's 32-row slab of onehot (fully coalesced, 1 granule each) ---
    {
        const float4* slab = (const float4*)(onehot + ((size_t)cid << 11));
        int r  = tid >> 4;             // row within slab (0..31)
        int c4 = (tid & 15) << 2;      // expert base of this quad
        float4 v = slab[tid];
        int sel = -1;
        if (v.x > 0.5f) sel = c4 + 0;
        if (v.y > 0.5f) sel = c4 + 1;
        if (v.z > 0.5f) sel = c4 + 2;
        if (v.w > 0.5f) sel = c4 + 3;
        if (sel >= 0) g_sel[cid * 32 + r] = sel;
    }
    if (tid < NHALF) s_bias[tid] = Bw[(e << 8) + n0 + tid];

    __threadfence();       // publish g_sel slice (gpu scope)
    __syncthreads();       // all decode writes + fences done; s_cnt init visible
    if (tid == 0) atomicAdd(&g_arrive, 1);

    if (tid < 256) {
        // ---- warps 0-7: convert W tile [256k][128n] to bf16 hi/lo swizzled ----
        const float* We = W + ((size_t)e << 16) + n0;
#pragma unroll
        for (int it = 0; it < 16; it++) {
            int u  = tid + 256 * it;    // 0..4095 granules (8 floats)
            int k  = u >> 4;
            int nc = u & 15;
            const float* src = We + ((size_t)k << 8) + (nc << 3);
            float4 v0 = *(const float4*)(src);
            float4 v1 = *(const float4*)(src + 4);
            uint32_t h0 = bf2(v0.x, v0.y), h1 = bf2(v0.z, v0.w);
            uint32_t h2 = bf2(v1.x, v1.y), h3 = bf2(v1.z, v1.w);
            uint32_t l0 = bf2(v0.x - bflo_f(h0), v0.y - bfhi_f(h0));
            uint32_t l1 = bf2(v0.z - bflo_f(h1), v0.w - bfhi_f(h1));
            uint32_t l2 = bf2(v1.x - bflo_f(h2), v1.y - bfhi_f(h2));
            uint32_t l3 = bf2(v1.z - bflo_f(h3), v1.w - bfhi_f(h3));
            uint32_t gsw = (uint32_t)((nc & 8) | ((nc & 7) ^ (k & 7)));
            uint32_t dst = ((uint32_t)k << 8) + (gsw << 4);
            *(uint4*)(smem + S_WH + dst) = make_uint4(h0, h1, h2, h3);
            *(uint4*)(smem + S_WL + dst) = make_uint4(l0, l1, l2, l3);
        }
    } else {
        // ---- warps 8-15: barrier, compact rows, stage x chunk 0 ----
        const int t = tid - 256;
        if (t == 0) {
            while (*(volatile int*)&g_arrive < NCTAS) { __nanosleep(64); }
        }
        asm volatile("bar.sync 3, 256;" ::: "memory");
        __threadfence();   // acquire side: g_sel writes visible

        int4 sv[4];
#pragma unroll
        for (int j = 0; j < 4; j++)
            sv[j] = ((const int4*)g_sel)[t + 256 * j];
#pragma unroll
        for (int j = 0; j < 4; j++) {
            int rb = (t + 256 * j) << 2;
            if (sv[j].x == e) { int p = atomicAdd(s_cnt, 1); if (p < RCAP) s_rows[p] = rb + 0; }
            if (sv[j].y == e) { int p = atomicAdd(s_cnt, 1); if (p < RCAP) s_rows[p] = rb + 1; }
            if (sv[j].z == e) { int p = atomicAdd(s_cnt, 1); if (p < RCAP) s_rows[p] = rb + 2; }
            if (sv[j].w == e) { int p = atomicAdd(s_cnt, 1); if (p < RCAP) s_rows[p] = rb + 3; }
        }
        asm volatile("bar.sync 3, 256;" ::: "memory");   // s_rows complete
        const int nrows0 = min(min(*s_cnt, RCAP), MCH);

        // stage x chunk 0: [96m][256k] fp32 -> bf16 hi/lo swizzled
#pragma unroll
        for (int it = 0; it < 12; it++) {
            int u = t + 256 * it;       // 0..3071
            int r = u >> 5;             // 0..95
            int c = u & 31;             // 8-float chunk
            float4 v0, v1;
            if (r < nrows0) {
                const float4* xr = (const float4*)(x + ((size_t)s_rows[r] << 8));
                v0 = xr[2 * c]; v1 = xr[2 * c + 1];
            } else {
                v0 = make_float4(0.f, 0.f, 0.f, 0.f);
                v1 = v0;
            }
            uint32_t h0 = bf2(v0.x, v0.y), h1 = bf2(v0.z, v0.w);
            uint32_t h2 = bf2(v1.x, v1.y), h3 = bf2(v1.z, v1.w);
            uint32_t l0 = bf2(v0.x - bflo_f(h0), v0.y - bfhi_f(h0));
            uint32_t l1 = bf2(v0.z - bflo_f(h1), v0.w - bfhi_f(h1));
            uint32_t l2 = bf2(v1.x - bflo_f(h2), v1.y - bfhi_f(h2));
            uint32_t l3 = bf2(v1.z - bflo_f(h3), v1.w - bfhi_f(h3));
            uint32_t gsw = (uint32_t)((c & 24) | ((c & 7) ^ (r & 7)));
            uint32_t dst = ((uint32_t)r << 9) + (gsw << 4);
            *(uint4*)(smem + S_XH + dst) = make_uint4(h0, h1, h2, h3);
            *(uint4*)(smem + S_XL + dst) = make_uint4(l0, l1, l2, l3);
        }
    }
    __syncthreads();   // W tiles + x chunk 0 + s_rows/s_cnt all ready

    const int cnt = min(*s_cnt, RCAP);

    // warp/lane geometry: warp grid 2m x 8n, warp tile 48m x 16n
    const int mw0 = (wid >> 3) * 48;               // 0 or 48
    const int nw0 = (wid & 7) * 16;                // 0,16,...,112
    const int lm    = lane & 15;
    const int lhalf = lane >> 4;
    const int l7    = lane & 7;

    uint32_t aBaseH[3], aBaseL[3];
#pragma unroll
    for (int i = 0; i < 3; i++) {
        uint32_t roff = (uint32_t)(mw0 + 16 * i + lm) << 9;
        aBaseH[i] = sb + S_XH + roff;
        aBaseL[i] = sb + S_XL + roff;
    }
    // B fragment: k-row = 16*ks + lm (256B rows); 16 cols via chunk ncA (per-lane)
    const int ncA = (wid & 7) * 2 + lhalf;         // 16B chunk 0..15
    const uint32_t gswBA = (uint32_t)((ncA & 8) | ((ncA & 7) ^ l7)) << 4;
    const uint32_t bBaseH = sb + S_WH + ((uint32_t)lm << 8) + gswBA;
    const uint32_t bBaseL = sb + S_WL + ((uint32_t)lm << 8) + gswBA;

    int m0 = 0;
    while (true) {
        // --- mma mainloop over staged chunk: D[3 m][2 n] fp32 ---
        uint32_t d[3][2][4];
#pragma unroll
        for (int i = 0; i < 3; i++)
#pragma unroll
            for (int j = 0; j < 2; j++)
#pragma unroll
                for (int q = 0; q < 4; q++) d[i][j][q] = 0u;

#pragma unroll 2
        for (int ks = 0; ks < 16; ks++) {
            int gA = 2 * ks + lhalf;
            uint32_t swA = (uint32_t)((gA & 24) | ((gA & 7) ^ l7)) << 4;
            uint32_t bK = (uint32_t)ks << 12;   // 16 k-rows * 256B

            uint32_t ah[3][4], al[3][4];
#pragma unroll
            for (int i = 0; i < 3; i++) {
                LDSM4(ah[i], aBaseH[i] + swA);
                LDSM4(al[i], aBaseL[i] + swA);
            }
            uint32_t bh[4], bl[4];
            LDSM4T(bh, bBaseH + bK);
            LDSM4T(bl, bBaseL + bK);

#pragma unroll
            for (int i = 0; i < 3; i++)
#pragma unroll
                for (int j = 0; j < 2; j++) {
                    MMA16816(d[i][j], ah[i], bh[2 * j], bh[2 * j + 1]);
                    MMA16816(d[i][j], ah[i], bl[2 * j], bl[2 * j + 1]);
                    MMA16816(d[i][j], al[i], bh[2 * j], bh[2 * j + 1]);
                }
        }

        // --- epilogue: add bias, scatter rows ---
#pragma unroll
        for (int i = 0; i < 3; i++) {
            int rlo = mw0 + 16 * i + (lane >> 2);
#pragma unroll
            for (int half = 0; half < 2; half++) {
                int m = m0 + rlo + 8 * half;
                if (m < cnt) {
                    float* op = out + ((size_t)s_rows[m] << 8) + n0;
#pragma unroll
                    for (int j = 0; j < 2; j++) {
                        int c = nw0 + 8 * j + 2 * (lane & 3);
                        float2 b = *(float2*)(s_bias + c);
                        float2 v;
                        v.x = __uint_as_float(d[i][j][2 * half + 0]) + b.x;
                        v.y = __uint_as_float(d[i][j][2 * half + 1]) + b.y;
                        *(float2*)(op + c) = v;
                    }
                }
            }
        }

        m0 += MCH;
        if (m0 >= cnt) break;

        // --- rare second chunk: stage by all 512 threads ---
        __syncthreads();
        const int nrows = min(MCH, cnt - m0);
#pragma unroll
        for (int it = 0; it < 6; it++) {
            int u = tid + NTHREADS * it;   // 0..3071
            int r = u >> 5;
            int c = u & 31;
            float4 v0, v1;
            if (r < nrows) {
                const float4* xr = (const float4*)(x + ((size_t)s_rows[m0 + r] << 8));
                v0 = xr[2 * c]; v1 = xr[2 * c + 1];
            } else {
                v0 = make_float4(0.f, 0.f, 0.f, 0.f);
                v1 = v0;
            }
            uint32_t h0 = bf2(v0.x, v0.y), h1 = bf2(v0.z, v0.w);
            uint32_t h2 = bf2(v1.x, v1.y), h3 = bf2(v1.z, v1.w);
            uint32_t l0 = bf2(v0.x - bflo_f(h0), v0.y - bfhi_f(h0));
            uint32_t l1 = bf2(v0.z - bflo_f(h1), v0.w - bfhi_f(h1));
            uint32_t l2 = bf2(v1.x - bflo_f(h2), v1.y - bfhi_f(h2));
            uint32_t l3 = bf2(v1.z - bflo_f(h3), v1.w - bfhi_f(h3));
            uint32_t gsw = (uint32_t)((c & 24) | ((c & 7) ^ (r & 7)));
            uint32_t dst = ((uint32_t)r << 9) + (gsw << 4);
            *(uint4*)(smem + S_XH + dst) = make_uint4(h0, h1, h2, h3);
            *(uint4*)(smem + S_XL + dst) = make_uint4(l0, l1, l2, l3);
        }
        __syncthreads();
    }

    // --- reset barrier counters for next graph replay ---
    if (tid == 0) {
        __threadfence();
        int od = atomicAdd(&g_done, 1);
        if (od == NCTAS - 1) {
            g_arrive = 0;
            g_done = 0;
            __threadfence();
        }
    }
}

// ---------------------------------------------------------------------------
extern "C" void kernel_launch(void* const* d_in, const int* in_sizes, int n_in,
                              void* d_out, int out_size) {
    const float* x      = (const float*)d_in[0];
    const float* onehot = (const float*)d_in[1];
    const float* W      = (const float*)d_in[2];
    const float* Bw     = (const float*)d_in[3];
    float* out          = (float*)d_out;

    cudaFuncSetAttribute(gemm_kernel,
                         cudaFuncAttributeMaxDynamicSharedMemorySize,
                         SMEM_BYTES);

    gemm_kernel<<<dim3(DOUT / NHALF, NEXP), NTHREADS, SMEM_BYTES>>>(
        x, onehot, W, Bw, out);
}

// round 16
// speedup vs baseline: 1.7391x; 1.1323x over previous
#include <cuda_runtime.h>
#include <cuda_bf16.h>
#include <cstdint>

// Problem constants
#define BATCH 4096
#define DIN   256
#define DOUT  256
#define NEXP  64

#define NHALF 128        // N cols per CTA (2 CTAs per expert)
#define MCH   96         // M rows per chunk
#define NTHREADS 512     // warps 0-7 producers, 8-15 consumers
#define RCAP  192
#define NCTAS 128        // one wave; co-resident

// smem byte offsets (dynamic)
#define S_WH   0                   // W hi: [256 k][128 n] bf16, 256B rows = 64KB
#define S_WL   65536               // W lo
#define S_XH   131072              // x hi: [96 m][256 k] bf16, 512B rows = 48KB
#define S_XL   180224              // x lo
#define S_BIAS 229376              // 128 floats
#define S_ROWS 229888              // RCAP ints
#define S_CNT  230656
#define SMEM_BYTES 230912

__device__ int g_sel[BATCH];   // decoded selector (rewritten every launch)
__device__ int g_arrive;       // decode barrier; reset by last-done CTA
__device__ int g_done;         // end-of-kernel arrival counter

// ---------------------------------------------------------------------------
__device__ __forceinline__ uint32_t bf2(float lo, float hi) {
    uint32_t r;
    asm("cvt.rn.bf16x2.f32 %0, %1, %2;" : "=r"(r) : "f"(hi), "f"(lo));
    return r;
}
__device__ __forceinline__ float bflo_f(uint32_t p) { return __uint_as_float(p << 16); }
__device__ __forceinline__ float bfhi_f(uint32_t p) { return __uint_as_float(p & 0xffff0000u); }

__device__ __forceinline__ uint32_t smem_to_u32(const void* p) {
    uint32_t a;
    asm("{ .reg .u64 t; cvta.to.shared.u64 t, %1; cvt.u32.u64 %0, t; }"
        : "=r"(a) : "l"(p));
    return a;
}

#define BAR_ARRIVE(ID) \
    asm volatile("bar.arrive %0, %1;" :: "r"(ID), "r"(512) : "memory")
#define BAR_WAIT(ID) \
    asm volatile("bar.sync %0, %1;" :: "r"(ID), "r"(512) : "memory")

#define LDSM4(R, ADDR) \
    asm volatile("ldmatrix.sync.aligned.m8n8.x4.shared.b16 {%0,%1,%2,%3}, [%4];" \
        : "=r"((R)[0]), "=r"((R)[1]), "=r"((R)[2]), "=r"((R)[3]) : "r"(ADDR))

#define LDSM4T(R, ADDR) \
    asm volatile("ldmatrix.sync.aligned.m8n8.x4.trans.shared.b16 {%0,%1,%2,%3}, [%4];" \
        : "=r"((R)[0]), "=r"((R)[1]), "=r"((R)[2]), "=r"((R)[3]) : "r"(ADDR))

#define MMA16816(D, A, B0, B1) \
    asm volatile("mma.sync.aligned.m16n8k16.row.col.f32.bf16.bf16.f32 " \
        "{%0,%1,%2,%3}, {%4,%5,%6,%7}, {%8,%9}, {%0,%1,%2,%3};" \
        : "+r"((D)[0]), "+r"((D)[1]), "+r"((D)[2]), "+r"((D)[3]) \
        : "r"((A)[0]), "r"((A)[1]), "r"((A)[2]), "r"((A)[3]), "r"(B0), "r"(B1))

// convert 8 floats (v0,v1) -> bf16 hi/lo uint4 pair and store swizzled
#define CVT_STORE(v0, v1, DSTH, DSTL) do {                                   \
    uint32_t h0 = bf2((v0).x, (v0).y), h1 = bf2((v0).z, (v0).w);             \
    uint32_t h2 = bf2((v1).x, (v1).y), h3 = bf2((v1).z, (v1).w);             \
    uint32_t l0 = bf2((v0).x - bflo_f(h0), (v0).y - bfhi_f(h0));             \
    uint32_t l1 = bf2((v0).z - bflo_f(h1), (v0).w - bfhi_f(h1));             \
    uint32_t l2 = bf2((v1).x - bflo_f(h2), (v1).y - bfhi_f(h2));             \
    uint32_t l3 = bf2((v1).z - bflo_f(h3), (v1).w - bfhi_f(h3));             \
    *(uint4*)(DSTH) = make_uint4(h0, h1, h2, h3);                            \
    *(uint4*)(DSTL) = make_uint4(l0, l1, l2, l3);                            \
} while (0)

// ---------------------------------------------------------------------------
// Single fused kernel. blockIdx.y = expert, blockIdx.x = n-half.
// Producer warps 0-7: decode/compact + convert W & stage x in 4 k-tiles.
// Consumer warps 8-15: per-k-tile 48x32-warp-tile HMMA + epilogue.
// 3-term bf16 split in fp32: xh*Wh + xh*Wl + xl*Wh.
// ---------------------------------------------------------------------------
__global__ void __launch_bounds__(NTHREADS, 1)
gemm_kernel(const float* __restrict__ x,
            const float* __restrict__ onehot,
            const float* __restrict__ W,
            const float* __restrict__ Bw,
            float* __restrict__ out) {
    extern __shared__ char smem[];
    const uint32_t sb = smem_to_u32(smem);
    float* s_bias = (float*)(smem + S_BIAS);
    int*   s_rows = (int*)(smem + S_ROWS);
    int*   s_cnt  = (int*)(smem + S_CNT);

    const int tid  = threadIdx.x;
    const int lane = tid & 31;
    const int wid  = tid >> 5;
    const int e    = blockIdx.y;
    const int n0   = blockIdx.x * NHALF;
    const int cid  = blockIdx.y * gridDim.x + blockIdx.x;   // 0..127

    if (tid == 0) *s_cnt = 0;

    // --- decode this CTA's 32-row slab of onehot (coalesced, 1 granule/thread) ---
    {
        const float4* slab = (const float4*)(onehot + ((size_t)cid << 11));
        int r  = tid >> 4;             // row within slab (0..31)
        int c4 = (tid & 15) << 2;      // expert base of this quad
        float4 v = slab[tid];
        int sel = -1;
        if (v.x > 0.5f) sel = c4 + 0;
        if (v.y > 0.5f) sel = c4 + 1;
        if (v.z > 0.5f) sel = c4 + 2;
        if (v.w > 0.5f) sel = c4 + 3;
        if (sel >= 0) g_sel[cid * 32 + r] = sel;
    }
    if (tid < NHALF) s_bias[tid] = Bw[(e << 8) + n0 + tid];

    __threadfence();       // publish g_sel slice
    __syncthreads();       // decode done; s_cnt init visible
    if (tid == 0) atomicAdd(&g_arrive, 1);

    const float* We = W + ((size_t)e << 16) + n0;

    int cnt;

    if (tid < 256) {
        // ================= PRODUCERS (warps 0-7) =================
        // W k-tile 0 while the global decode barrier settles
        {
#pragma unroll
            for (int j = 0; j < 4; j++) {
                int gi = tid + 256 * j;           // 0..1023
                int k  = gi >> 4;                 // tile 0: k 0..63
                int nc = gi & 15;
                const float* src = We + ((size_t)k << 8) + (nc << 3);
                float4 v0 = *(const float4*)(src);
                float4 v1 = *(const float4*)(src + 4);
                uint32_t gsw = (uint32_t)((nc & 8) | ((nc & 7) ^ (k & 7)));
                uint32_t dst = ((uint32_t)k << 8) + (gsw << 4);
                CVT_STORE(v0, v1, smem + S_WH + dst, smem + S_WL + dst);
            }
        }
        // global barrier: all CTAs decoded
        if (tid == 0) {
            while (*(volatile int*)&g_arrive < NCTAS) { __nanosleep(64); }
        }
        asm volatile("bar.sync 3, 256;" ::: "memory");
        __threadfence();   // acquire g_sel

        // compact this expert's rows
        int4 sv[4];
#pragma unroll
        for (int j = 0; j < 4; j++)
            sv[j] = ((const int4*)g_sel)[tid + 256 * j];
#pragma unroll
        for (int j = 0; j < 4; j++) {
            int rb = (tid + 256 * j) << 2;
            if (sv[j].x == e) { int p = atomicAdd(s_cnt, 1); if (p < RCAP) s_rows[p] = rb + 0; }
            if (sv[j].y == e) { int p = atomicAdd(s_cnt, 1); if (p < RCAP) s_rows[p] = rb + 1; }
            if (sv[j].z == e) { int p = atomicAdd(s_cnt, 1); if (p < RCAP) s_rows[p] = rb + 2; }
            if (sv[j].w == e) { int p = atomicAdd(s_cnt, 1); if (p < RCAP) s_rows[p] = rb + 3; }
        }
        asm volatile("bar.sync 3, 256;" ::: "memory");   // s_rows complete
        cnt = min(*s_cnt, RCAP);
        const int nr0 = min(cnt, MCH);

        // chunk 0, tiles 0..3: x tile (+W tile for t>=1), then arrive
#pragma unroll 1
        for (int t = 0; t < 4; t++) {
            if (t > 0) {
#pragma unroll
                for (int j = 0; j < 4; j++) {
                    int gi = tid + 256 * j;
                    int k  = 64 * t + (gi >> 4);
                    int nc = gi & 15;
                    const float* src = We + ((size_t)k << 8) + (nc << 3);
                    float4 v0 = *(const float4*)(src);
                    float4 v1 = *(const float4*)(src + 4);
                    uint32_t gsw = (uint32_t)((nc & 8) | ((nc & 7) ^ (k & 7)));
                    uint32_t dst = ((uint32_t)k << 8) + (gsw << 4);
                    CVT_STORE(v0, v1, smem + S_WH + dst, smem + S_WL + dst);
                }
            }
#pragma unroll
            for (int j = 0; j < 3; j++) {
                int gi = tid + 256 * j;           // 0..767
                int r  = gi >> 3;                 // 0..95
                int c  = 8 * t + (gi & 7);        // global granule
                float4 v0, v1;
                if (r < nr0) {
                    const float4* xr = (const float4*)(x + ((size_t)s_rows[r] << 8));
                    v0 = xr[2 * c]; v1 = xr[2 * c + 1];
                } else {
                    v0 = make_float4(0.f, 0.f, 0.f, 0.f); v1 = v0;
                }
                uint32_t gsw = (uint32_t)((c & 24) | ((c & 7) ^ (r & 7)));
                uint32_t dst = ((uint32_t)r << 9) + (gsw << 4);
                CVT_STORE(v0, v1, smem + S_XH + dst, smem + S_XL + dst);
            }
            BAR_ARRIVE(4 + t);
        }

        // rare chunk 1
        if (cnt > MCH) {
            __syncthreads();
            const int nr1 = min(cnt - MCH, MCH);
#pragma unroll 1
            for (int t = 0; t < 4; t++) {
#pragma unroll
                for (int j = 0; j < 3; j++) {
                    int gi = tid + 256 * j;
                    int r  = gi >> 3;
                    int c  = 8 * t + (gi & 7);
                    float4 v0, v1;
                    if (r < nr1) {
                        const float4* xr = (const float4*)(x + ((size_t)s_rows[MCH + r] << 8));
                        v0 = xr[2 * c]; v1 = xr[2 * c + 1];
                    } else {
                        v0 = make_float4(0.f, 0.f, 0.f, 0.f); v1 = v0;
                    }
                    uint32_t gsw = (uint32_t)((c & 24) | ((c & 7) ^ (r & 7)));
                    uint32_t dst = ((uint32_t)r << 9) + (gsw << 4);
                    CVT_STORE(v0, v1, smem + S_XH + dst, smem + S_XL + dst);
                }
                BAR_ARRIVE(4 + t);
            }
        }
    } else {
        // ================= CONSUMERS (warps 8-15) =================
        const int cwid = wid - 8;                      // 0..7
        const int mw0 = (cwid >> 2) * 48;              // 0 or 48
        const int nw0 = (cwid & 3) * 32;               // 0,32,64,96
        const int lm    = lane & 15;
        const int lhalf = lane >> 4;
        const int l7    = lane & 7;

        uint32_t aBaseH[3], aBaseL[3];
#pragma unroll
        for (int i = 0; i < 3; i++) {
            uint32_t roff = (uint32_t)(mw0 + 16 * i + lm) << 9;
            aBaseH[i] = sb + S_XH + roff;
            aBaseL[i] = sb + S_XL + roff;
        }
        const int ncA = (cwid & 3) * 4 + lhalf;
        const int ncB = ncA + 2;
        const uint32_t gswBA = (uint32_t)((ncA & 8) | ((ncA & 7) ^ l7)) << 4;
        const uint32_t gswBB = (uint32_t)((ncB & 8) | ((ncB & 7) ^ l7)) << 4;
        const uint32_t bBaseH = sb + S_WH + ((uint32_t)lm << 8);
        const uint32_t bBaseL = sb + S_WL + ((uint32_t)lm << 8);

        int m0 = 0;
        cnt = 0;
#pragma unroll 1
        for (int chunk = 0; chunk < 2; chunk++) {
            uint32_t d[3][4][4];
#pragma unroll
            for (int i = 0; i < 3; i++)
#pragma unroll
                for (int j = 0; j < 4; j++)
#pragma unroll
                    for (int q = 0; q < 4; q++) d[i][j][q] = 0u;

#pragma unroll 1
            for (int t = 0; t < 4; t++) {
                BAR_WAIT(4 + t);
                if (t == 0 && chunk == 0) cnt = min(*s_cnt, RCAP);
#pragma unroll
                for (int kk = 0; kk < 4; kk++) {
                    int ks = 4 * t + kk;
                    int gA = 2 * ks + lhalf;
                    uint32_t swA = (uint32_t)((gA & 24) | ((gA & 7) ^ l7)) << 4;
                    uint32_t bK = (uint32_t)ks << 12;

                    uint32_t ah[3][4], al[3][4];
#pragma unroll
                    for (int i = 0; i < 3; i++) {
                        LDSM4(ah[i], aBaseH[i] + swA);
                        LDSM4(al[i], aBaseL[i] + swA);
                    }
                    uint32_t bh[8], bl[8];
                    LDSM4T(bh,     bBaseH + bK + gswBA);
                    LDSM4T(bh + 4, bBaseH + bK + gswBB);
                    LDSM4T(bl,     bBaseL + bK + gswBA);
                    LDSM4T(bl + 4, bBaseL + bK + gswBB);

#pragma unroll
                    for (int i = 0; i < 3; i++)
#pragma unroll
                        for (int j = 0; j < 4; j++) {
                            MMA16816(d[i][j], ah[i], bh[2 * j], bh[2 * j + 1]);
                            MMA16816(d[i][j], ah[i], bl[2 * j], bl[2 * j + 1]);
                            MMA16816(d[i][j], al[i], bh[2 * j], bh[2 * j + 1]);
                        }
                }
            }

            // epilogue
#pragma unroll
            for (int i = 0; i < 3; i++) {
                int rlo = mw0 + 16 * i + (lane >> 2);
#pragma unroll
                for (int half = 0; half < 2; half++) {
                    int m = m0 + rlo + 8 * half;
                    if (m < cnt) {
                        float* op = out + ((size_t)s_rows[m] << 8) + n0;
#pragma unroll
                        for (int j = 0; j < 4; j++) {
                            int c = nw0 + 8 * j + 2 * (lane & 3);
                            float2 b = *(float2*)(s_bias + c);
                            float2 v;
                            v.x = __uint_as_float(d[i][j][2 * half + 0]) + b.x;
                            v.y = __uint_as_float(d[i][j][2 * half + 1]) + b.y;
                            *(float2*)(op + c) = v;
                        }
                    }
                }
            }

            m0 += MCH;
            if (cnt > MCH && chunk == 0) {
                __syncthreads();   // matches producer pre-chunk-1 sync
            } else {
                break;
            }
        }
    }

    // --- reset barrier counters for next graph replay ---
    __syncthreads();
    if (tid == 0) {
        __threadfence();
        int od = atomicAdd(&g_done, 1);
        if (od == NCTAS - 1) {
            g_arrive = 0;
            g_done = 0;
            __threadfence();
        }
    }
}

// ---------------------------------------------------------------------------
extern "C" void kernel_launch(void* const* d_in, const int* in_sizes, int n_in,
                              void* d_out, int out_size) {
    const float* x      = (const float*)d_in[0];
    const float* onehot = (const float*)d_in[1];
    const float* W      = (const float*)d_in[2];
    const float* Bw     = (const float*)d_in[3];
    float* out          = (float*)d_out;

    cudaFuncSetAttribute(gemm_kernel,
                         cudaFuncAttributeMaxDynamicSharedMemorySize,
                         SMEM_BYTES);

    gemm_kernel<<<dim3(DOUT / NHALF, NEXP), NTHREADS, SMEM_BYTES>>>(
        x, onehot, W, Bw, out);
}